// round 2
// baseline (speedup 1.0000x reference)
#include <cuda_runtime.h>
#include <cstdint>

#define NW     16384
#define MAXLEN 16
#define VOCAB  128
#define EMB    64
#define HID    256
#define G4     1024

// ---------------- static device state (no allocation) ----------------
__device__ float d_P[2 * VOCAB * G4];            // char->gate table incl. biases (1MB)
__device__ float d_H[2][2 * HID * NW];           // ping-pong h: [buf][dir*HID*NW + k*NW + slot]
__device__ float d_C[(size_t)2 * NW * HID];      // c: [dir][slot][j]
__device__ float d_Hfin[(size_t)2 * NW * HID];   // final h: [dir][slot][j]
__device__ int   d_hist[MAXLEN + 2];
__device__ int   d_cursor[MAXLEN + 2];
__device__ int   d_offset[MAXLEN + 2];
__device__ int   d_nactive[MAXLEN];
__device__ int   d_word_of_slot[NW];
__device__ unsigned char d_slot_len[NW];
__device__ unsigned char d_chars[2][MAXLEN][NW];

// ---------------- helpers ----------------
__device__ __forceinline__ unsigned long long dup2(float x) {
    unsigned long long r; unsigned int u = __float_as_uint(x);
    asm("mov.b64 %0, {%1, %2};" : "=l"(r) : "r"(u), "r"(u));
    return r;
}
__device__ __forceinline__ void unpack2(unsigned long long v, float& lo, float& hi) {
    unsigned int a, b;
    asm("mov.b64 {%0, %1}, %2;" : "=r"(a), "=r"(b) : "l"(v));
    lo = __uint_as_float(a); hi = __uint_as_float(b);
}
__device__ __forceinline__ float sigm(float x) {
    return __fdividef(1.f, 1.f + __expf(-x));
}

// ---------------- setup ----------------
__global__ void k_init() {
    int i = threadIdx.x;
    if (i <= MAXLEN + 1) { d_hist[i] = 0; d_cursor[i] = 0; }
}

__global__ void k_zero() {
    float4* h4 = reinterpret_cast<float4*>(&d_H[0][0]);
    float4* c4 = reinterpret_cast<float4*>(&d_C[0]);
    const int nh = 2 * HID * NW / 4, nc = 2 * NW * HID / 4;
    int stride = gridDim.x * blockDim.x;
    for (int i = blockIdx.x * blockDim.x + threadIdx.x; i < nh; i += stride)
        h4[i] = make_float4(0.f, 0.f, 0.f, 0.f);
    for (int i = blockIdx.x * blockDim.x + threadIdx.x; i < nc; i += stride)
        c4[i] = make_float4(0.f, 0.f, 0.f, 0.f);
}

__global__ void k_hist(const int* __restrict__ lengths) {
    int w = blockIdx.x * blockDim.x + threadIdx.x;
    if (w < NW) atomicAdd(&d_hist[lengths[w]], 1);
}

__global__ void k_scan() {
    int off = 0;
    for (int L = MAXLEN; L >= 1; L--) { d_offset[L] = off; off += d_hist[L]; }
    for (int t = 0; t < MAXLEN; t++) {
        int n = 0;
        for (int L = t + 1; L <= MAXLEN; L++) n += d_hist[L];
        d_nactive[t] = n;
    }
}

__global__ void k_scatter(const int* __restrict__ lengths, const int* __restrict__ char_ids) {
    int w = blockIdx.x * blockDim.x + threadIdx.x;
    if (w >= NW) return;
    int len = lengths[w];
    int pos = d_offset[len] + atomicAdd(&d_cursor[len], 1);
    d_word_of_slot[pos] = w;
    d_slot_len[pos] = (unsigned char)len;
#pragma unroll
    for (int t = 0; t < MAXLEN; t++) {
        d_chars[0][t][pos] = (unsigned char)char_ids[w * MAXLEN + t];
        int r = len - 1 - t; if (r < 0) r = 0;
        d_chars[1][t][pos] = (unsigned char)char_ids[w * MAXLEN + r];
    }
}

// P[d][v][row] = emb[v] . W_ih[row] + b_ih[row] + b_hh[row]
__global__ void k_ptable(const float* __restrict__ emb,
                         const float* __restrict__ WihF, const float* __restrict__ bihF,
                         const float* __restrict__ bhhF,
                         const float* __restrict__ WihB, const float* __restrict__ bihB,
                         const float* __restrict__ bhhB) {
    int v = blockIdx.x, d = blockIdx.y;
    const float* Wih = d ? WihB : WihF;
    const float* bih = d ? bihB : bihF;
    const float* bhh = d ? bhhB : bhhF;
    __shared__ float e[EMB];
    if (threadIdx.x < EMB) e[threadIdx.x] = emb[v * EMB + threadIdx.x];
    __syncthreads();
#pragma unroll
    for (int q = 0; q < 4; q++) {
        int j = threadIdx.x + q * 256;
        const float* wr = &Wih[j * EMB];
        float s = 0.f;
#pragma unroll
        for (int k = 0; k < EMB; k += 4) {
            float4 wv = *reinterpret_cast<const float4*>(&wr[k]);
            s += e[k] * wv.x + e[k + 1] * wv.y + e[k + 2] * wv.z + e[k + 3] * wv.w;
        }
        d_P[(d * VOCAB + v) * G4 + j] = s + bih[j] + bhh[j];
    }
}

// ---------------- fused recurrent step: GEMM (f32x2) + LSTM cell ----------------
// Block: 64 slots x 32 j-cols x 4 gates. Thread (tid): jl = tid&31 (j col),
// sg = tid>>5 (8-slot group). Accumulators: 4 slot-pairs x 4 gates, packed f32x2.
__global__ void __launch_bounds__(256, 2)
k_step(const float* __restrict__ WhhF, const float* __restrict__ WhhB, int t) {
    const int nact = d_nactive[t];
    const int slot0 = blockIdx.x * 64;
    if (slot0 >= nact) return;
    const int j0 = blockIdx.y * 32;
    const int dir = blockIdx.z;
    const float* __restrict__ W = dir ? WhhB : WhhF;            // [1024][256]
    const int rb = t & 1, wbuf = rb ^ 1;
    const float* __restrict__ Hr = d_H[rb]   + (size_t)dir * HID * NW;
    float*       __restrict__ Hw = d_H[wbuf] + (size_t)dir * HID * NW;

    __shared__ __align__(16) float Hs[16][64];
    __shared__ __align__(16) float Ws[16][4][32];

    const int tid = threadIdx.x;
    const int jl = tid & 31, sg = tid >> 5;
    const int j = j0 + jl;

    unsigned long long acc[4][4];
#pragma unroll
    for (int p = 0; p < 4; p++)
#pragma unroll
        for (int g = 0; g < 4; g++) acc[p][g] = 0ull;

    for (int kc = 0; kc < HID; kc += 16) {
#pragma unroll
        for (int i = 0; i < 4; i++) {
            int e = tid + i * 256, kk = e >> 6, w = e & 63;
            Hs[kk][w] = Hr[(size_t)(kc + kk) * NW + slot0 + w];
        }
#pragma unroll
        for (int i = 0; i < 2; i++) {
            int f = tid + i * 256;
            int row = f >> 2, kq = (f & 3) << 2;
            int g = row >> 5, jw = row & 31;
            float4 v = *reinterpret_cast<const float4*>(
                &W[(size_t)((g << 8) + j0 + jw) * HID + kc + kq]);
            Ws[kq + 0][g][jw] = v.x; Ws[kq + 1][g][jw] = v.y;
            Ws[kq + 2][g][jw] = v.z; Ws[kq + 3][g][jw] = v.w;
        }
        __syncthreads();
#pragma unroll
        for (int k = 0; k < 16; k++) {
            const ulonglong2* hp = reinterpret_cast<const ulonglong2*>(&Hs[k][sg * 8]);
            ulonglong2 hA = hp[0], hB = hp[1];
            unsigned long long wd[4];
#pragma unroll
            for (int g = 0; g < 4; g++) wd[g] = dup2(Ws[k][g][jl]);
#pragma unroll
            for (int g = 0; g < 4; g++) {
                asm("fma.rn.f32x2 %0, %1, %2, %0;" : "+l"(acc[0][g]) : "l"(hA.x), "l"(wd[g]));
                asm("fma.rn.f32x2 %0, %1, %2, %0;" : "+l"(acc[1][g]) : "l"(hA.y), "l"(wd[g]));
                asm("fma.rn.f32x2 %0, %1, %2, %0;" : "+l"(acc[2][g]) : "l"(hB.x), "l"(wd[g]));
                asm("fma.rn.f32x2 %0, %1, %2, %0;" : "+l"(acc[3][g]) : "l"(hB.y), "l"(wd[g]));
            }
        }
        __syncthreads();
    }

    // epilogue: full LSTM cell, thread-local gates
    float hout[8];
#pragma unroll
    for (int p = 0; p < 4; p++) {
        float gi[2], gf[2], gg[2], go[2];
        unpack2(acc[p][0], gi[0], gi[1]);
        unpack2(acc[p][1], gf[0], gf[1]);
        unpack2(acc[p][2], gg[0], gg[1]);
        unpack2(acc[p][3], go[0], go[1]);
#pragma unroll
        for (int half = 0; half < 2; half++) {
            int s = slot0 + sg * 8 + 2 * p + half;
            float h2 = 0.f;
            if (s < nact) {                         // sorted: s < nact <=> t < len(s)
                int v = d_chars[dir][t][s];
                const float* Pv = &d_P[((dir << 7) + v) << 10];
                float ai = gi[half] + Pv[j];
                float af = gf[half] + Pv[256 + j];
                float ag = gg[half] + Pv[512 + j];
                float ao = go[half] + Pv[768 + j];
                float* cp = &d_C[((size_t)dir * NW + s) * HID + j];
                float c2 = sigm(af) * (*cp) + sigm(ai) * tanhf(ag);
                h2 = sigm(ao) * tanhf(c2);
                *cp = c2;
                if (t == (int)d_slot_len[s] - 1)
                    d_Hfin[((size_t)dir * NW + s) * HID + j] = h2;
            }
            hout[2 * p + half] = h2;
        }
    }
    float* hw = &Hw[(size_t)j * NW + slot0 + sg * 8];
    *reinterpret_cast<float4*>(hw)     = make_float4(hout[0], hout[1], hout[2], hout[3]);
    *reinterpret_cast<float4*>(hw + 4) = make_float4(hout[4], hout[5], hout[6], hout[7]);
}

// ---------------- gather output: out[w][dir*256+j] ----------------
__global__ void k_out(float* __restrict__ out) {
    int s = blockIdx.x;
    int tid = threadIdx.x;           // 512 threads: dir = tid>>8, j = tid&255
    int w = d_word_of_slot[s];
    int dir = tid >> 8, j = tid & 255;
    out[(size_t)w * 512 + tid] = d_Hfin[((size_t)dir * NW + s) * HID + j];
}

// ---------------- launch ----------------
extern "C" void kernel_launch(void* const* d_in, const int* in_sizes, int n_in,
                              void* d_out, int out_size) {
    const int*   char_ids = (const int*)d_in[0];
    const int*   lengths  = (const int*)d_in[1];
    const float* emb      = (const float*)d_in[2];
    const float* WihF = (const float*)d_in[3];
    const float* WhhF = (const float*)d_in[4];
    const float* bihF = (const float*)d_in[5];
    const float* bhhF = (const float*)d_in[6];
    const float* WihB = (const float*)d_in[7];
    const float* WhhB = (const float*)d_in[8];
    const float* bihB = (const float*)d_in[9];
    const float* bhhB = (const float*)d_in[10];
    float* out = (float*)d_out;

    k_init<<<1, 32>>>();
    k_zero<<<2048, 256>>>();
    k_ptable<<<dim3(VOCAB, 2), 256>>>(emb, WihF, bihF, bhhF, WihB, bihB, bhhB);
    k_hist<<<NW / 256, 256>>>(lengths);
    k_scan<<<1, 1>>>();
    k_scatter<<<NW / 256, 256>>>(lengths, char_ids);
    for (int t = 0; t < MAXLEN; t++)
        k_step<<<dim3(NW / 64, 8, 2), 256>>>(WhhF, WhhB, t);
    k_out<<<NW, 512>>>(out);
}

// round 3
// speedup vs baseline: 1.5696x; 1.5696x over previous
#include <cuda_runtime.h>
#include <cuda_bf16.h>
#include <cstdint>

#define NW     16384
#define MAXLEN 16
#define VOCAB  128
#define EMB    64
#define HID    256
#define G4     1024
#define PITCH  36   // bf16 elems per smem row (even, conflict-free for frag loads)

// ---------------- static device state (no allocation) ----------------
__device__ float d_P[2 * VOCAB * G4];                 // char->gate table incl. biases
__device__ float d_H[2][2 * HID * NW];                // ping-pong h: [buf][dir*HID*NW + k*NW + slot]
__device__ float d_C[(size_t)2 * NW * HID];           // c: [dir][slot][j]
__device__ float d_Hfin[(size_t)2 * NW * HID];        // final h: [dir][slot][j]
__device__ __nv_bfloat16 d_Whi[2][G4 * HID];          // W split hi: [dir][row][k]
__device__ __nv_bfloat16 d_Wlo[2][G4 * HID];          // W split lo
__device__ int   d_hist[MAXLEN + 2];
__device__ int   d_cursor[MAXLEN + 2];
__device__ int   d_offset[MAXLEN + 2];
__device__ int   d_nactive[MAXLEN];
__device__ int   d_word_of_slot[NW];
__device__ unsigned char d_slot_len[NW];
__device__ unsigned char d_chars[2][MAXLEN][NW];

// ---------------- helpers ----------------
__device__ __forceinline__ float sigm(float x) {
    return __fdividef(1.f, 1.f + __expf(-x));
}
__device__ __forceinline__ void mma_bf16(float c[4], const uint32_t a[4],
                                         uint32_t b0, uint32_t b1) {
    asm volatile(
        "mma.sync.aligned.m16n8k16.row.col.f32.bf16.bf16.f32 "
        "{%0,%1,%2,%3}, {%4,%5,%6,%7}, {%8,%9}, {%0,%1,%2,%3};"
        : "+f"(c[0]), "+f"(c[1]), "+f"(c[2]), "+f"(c[3])
        : "r"(a[0]), "r"(a[1]), "r"(a[2]), "r"(a[3]), "r"(b0), "r"(b1));
}
__device__ __forceinline__ uint32_t pack2(__nv_bfloat16 a, __nv_bfloat16 b) {
    __nv_bfloat162 v; v.x = a; v.y = b;
    return *reinterpret_cast<uint32_t*>(&v);
}

// ---------------- setup ----------------
__global__ void k_init() {
    int i = threadIdx.x;
    if (i <= MAXLEN + 1) { d_hist[i] = 0; d_cursor[i] = 0; }
}

__global__ void k_hist(const int* __restrict__ lengths) {
    int w = blockIdx.x * blockDim.x + threadIdx.x;
    if (w < NW) atomicAdd(&d_hist[lengths[w]], 1);
}

__global__ void k_scan() {
    int off = 0;
    for (int L = MAXLEN; L >= 1; L--) { d_offset[L] = off; off += d_hist[L]; }
    for (int t = 0; t < MAXLEN; t++) {
        int n = 0;
        for (int L = t + 1; L <= MAXLEN; L++) n += d_hist[L];
        d_nactive[t] = n;
    }
}

__global__ void k_scatter(const int* __restrict__ lengths, const int* __restrict__ char_ids) {
    int w = blockIdx.x * blockDim.x + threadIdx.x;
    if (w >= NW) return;
    int len = lengths[w];
    int pos = d_offset[len] + atomicAdd(&d_cursor[len], 1);
    d_word_of_slot[pos] = w;
    d_slot_len[pos] = (unsigned char)len;
#pragma unroll
    for (int t = 0; t < MAXLEN; t++) {
        d_chars[0][t][pos] = (unsigned char)char_ids[w * MAXLEN + t];
        int r = len - 1 - t; if (r < 0) r = 0;
        d_chars[1][t][pos] = (unsigned char)char_ids[w * MAXLEN + r];
    }
}

// W -> bf16 hi/lo split (once per launch)
__global__ void k_wsplit(const float* __restrict__ WhhF, const float* __restrict__ WhhB) {
    int i = blockIdx.x * blockDim.x + threadIdx.x;  // over 2*G4*HID
    int dir = i / (G4 * HID);
    int e = i % (G4 * HID);
    float x = (dir ? WhhB : WhhF)[e];
    __nv_bfloat16 hi = __float2bfloat16_rn(x);
    __nv_bfloat16 lo = __float2bfloat16_rn(x - __bfloat162float(hi));
    d_Whi[dir][e] = hi;
    d_Wlo[dir][e] = lo;
}

// P[d][v][row] = emb[v] . W_ih[row] + b_ih[row] + b_hh[row]
__global__ void k_ptable(const float* __restrict__ emb,
                         const float* __restrict__ WihF, const float* __restrict__ bihF,
                         const float* __restrict__ bhhF,
                         const float* __restrict__ WihB, const float* __restrict__ bihB,
                         const float* __restrict__ bhhB) {
    int v = blockIdx.x, d = blockIdx.y;
    const float* Wih = d ? WihB : WihF;
    const float* bih = d ? bihB : bihF;
    const float* bhh = d ? bhhB : bhhF;
    __shared__ float e[EMB];
    if (threadIdx.x < EMB) e[threadIdx.x] = emb[v * EMB + threadIdx.x];
    __syncthreads();
#pragma unroll
    for (int q = 0; q < 4; q++) {
        int j = threadIdx.x + q * 256;
        const float* wr = &Wih[j * EMB];
        float s = 0.f;
#pragma unroll
        for (int k = 0; k < EMB; k += 4) {
            float4 wv = *reinterpret_cast<const float4*>(&wr[k]);
            s += e[k] * wv.x + e[k + 1] * wv.y + e[k + 2] * wv.z + e[k + 3] * wv.w;
        }
        d_P[(d * VOCAB + v) * G4 + j] = s + bih[j] + bhh[j];
    }
}

// ---------------- fused recurrent step: bf16x3 HMMA GEMM + LSTM cell ----------------
// Block: 64 slots x 32 j x 4 gates. 8 warps: warp = 16 slots x 16 j.
// acc[g][nhalf][4] = m16n8 fp32 fragments, all 4 gates in the same lane
// for the same (slot, j) -> thread-local LSTM cell epilogue.
__global__ void __launch_bounds__(256, 2)
k_step(int t) {
    const int nact = d_nactive[t];
    const int slot0 = blockIdx.x * 64;
    if (slot0 >= nact) return;
    const int j0 = blockIdx.y * 32;
    const int dir = blockIdx.z;
    const int rb = t & 1;
    const float* __restrict__ Hr = d_H[rb]     + (size_t)dir * HID * NW;
    float*       __restrict__ Hw = d_H[rb ^ 1] + (size_t)dir * HID * NW;
    const __nv_bfloat16* __restrict__ Whi = d_Whi[dir];
    const __nv_bfloat16* __restrict__ Wlo = d_Wlo[dir];

    __shared__ __align__(16) __nv_bfloat16 As[2][64 * PITCH];
    __shared__ __align__(16) __nv_bfloat16 Ws[2][128 * PITCH];

    const int tid = threadIdx.x;
    const int lane = tid & 31, warp = tid >> 5;
    const int ws = warp & 3;        // slot block (16)
    const int wj = warp >> 2;       // j block (16)
    const int g4 = lane >> 2;       // group id 0..7
    const int t4 = lane & 3;        // 0..3

    float acc[4][2][4];
#pragma unroll
    for (int g = 0; g < 4; g++)
#pragma unroll
        for (int nh = 0; nh < 2; nh++)
#pragma unroll
            for (int r = 0; r < 4; r++) acc[g][nh][r] = 0.f;

    if (t > 0) {
        for (int kc = 0; kc < HID; kc += 32) {
            // ---- stage H chunk (fp32 -> bf16 hi/lo), smem [slot][k], pitch 36 ----
#pragma unroll
            for (int i = 0; i < 4; i++) {
                int p = tid + i * 256;            // 1024 k-pairs
                int k2 = p >> 6, s = p & 63;      // k = 2*k2
                int k = 2 * k2;
                float x0 = Hr[(size_t)(kc + k) * NW + slot0 + s];
                float x1 = Hr[(size_t)(kc + k + 1) * NW + slot0 + s];
                __nv_bfloat16 h0 = __float2bfloat16_rn(x0);
                __nv_bfloat16 h1 = __float2bfloat16_rn(x1);
                __nv_bfloat16 l0 = __float2bfloat16_rn(x0 - __bfloat162float(h0));
                __nv_bfloat16 l1 = __float2bfloat16_rn(x1 - __bfloat162float(h1));
                *reinterpret_cast<uint32_t*>(&As[0][s * PITCH + k]) = pack2(h0, h1);
                *reinterpret_cast<uint32_t*>(&As[1][s * PITCH + k]) = pack2(l0, l1);
            }
            // ---- stage W chunk: rows r = g*32+jw -> W row g*256 + j0 + jw ----
#pragma unroll
            for (int sp = 0; sp < 2; sp++) {
                const __nv_bfloat16* Wg = sp ? Wlo : Whi;
#pragma unroll
                for (int i = 0; i < 8; i++) {
                    int e = tid + i * 256;        // 2048 32-bit words
                    int r = e >> 4, kw = e & 15;
                    int wrow = ((r >> 5) << 8) + j0 + (r & 31);
                    uint32_t v = *reinterpret_cast<const uint32_t*>(
                        &Wg[(size_t)wrow * HID + kc + 2 * kw]);
                    *reinterpret_cast<uint32_t*>(&Ws[sp][r * PITCH + 2 * kw]) = v;
                }
            }
            __syncthreads();
            // ---- compute: 2 k-sub (16) x 4 gates x 2 n-halves x 3 split terms ----
#pragma unroll
            for (int kk = 0; kk < 32; kk += 16) {
                uint32_t ah[4], al[4];
                int arow = ws * 16 + g4;
                int acol = kk + 2 * t4;
                ah[0] = *reinterpret_cast<const uint32_t*>(&As[0][arow * PITCH + acol]);
                ah[1] = *reinterpret_cast<const uint32_t*>(&As[0][(arow + 8) * PITCH + acol]);
                ah[2] = *reinterpret_cast<const uint32_t*>(&As[0][arow * PITCH + acol + 8]);
                ah[3] = *reinterpret_cast<const uint32_t*>(&As[0][(arow + 8) * PITCH + acol + 8]);
                al[0] = *reinterpret_cast<const uint32_t*>(&As[1][arow * PITCH + acol]);
                al[1] = *reinterpret_cast<const uint32_t*>(&As[1][(arow + 8) * PITCH + acol]);
                al[2] = *reinterpret_cast<const uint32_t*>(&As[1][arow * PITCH + acol + 8]);
                al[3] = *reinterpret_cast<const uint32_t*>(&As[1][(arow + 8) * PITCH + acol + 8]);
#pragma unroll
                for (int g = 0; g < 4; g++) {
#pragma unroll
                    for (int nh = 0; nh < 2; nh++) {
                        int brow = g * 32 + wj * 16 + nh * 8 + g4;
                        int bcol = kk + 2 * t4;
                        uint32_t bh0 = *reinterpret_cast<const uint32_t*>(&Ws[0][brow * PITCH + bcol]);
                        uint32_t bh1 = *reinterpret_cast<const uint32_t*>(&Ws[0][brow * PITCH + bcol + 8]);
                        uint32_t bl0 = *reinterpret_cast<const uint32_t*>(&Ws[1][brow * PITCH + bcol]);
                        uint32_t bl1 = *reinterpret_cast<const uint32_t*>(&Ws[1][brow * PITCH + bcol + 8]);
                        mma_bf16(acc[g][nh], ah, bh0, bh1);
                        mma_bf16(acc[g][nh], ah, bl0, bl1);
                        mma_bf16(acc[g][nh], al, bh0, bh1);
                    }
                }
            }
            __syncthreads();
        }
    }

    // ---- epilogue: LSTM cell, all 4 gates thread-local ----
#pragma unroll
    for (int nh = 0; nh < 2; nh++) {
#pragma unroll
        for (int rh = 0; rh < 2; rh++) {
            int s = slot0 + ws * 16 + g4 + rh * 8;
            if (s >= nact) continue;
            int v = d_chars[dir][t][s];
            const float* Pv = &d_P[((dir << 7) + v) << 10];
            bool last = (t == (int)d_slot_len[s] - 1);
#pragma unroll
            for (int cp = 0; cp < 2; cp++) {
                int j = j0 + wj * 16 + nh * 8 + 2 * t4 + cp;
                int ci = rh * 2 + cp;
                float ai = acc[0][nh][ci] + Pv[j];
                float af = acc[1][nh][ci] + Pv[256 + j];
                float ag = acc[2][nh][ci] + Pv[512 + j];
                float ao = acc[3][nh][ci] + Pv[768 + j];
                float* cptr = &d_C[((size_t)dir * NW + s) * HID + j];
                float cprev = (t == 0) ? 0.f : *cptr;
                float c2 = sigm(af) * cprev + sigm(ai) * tanhf(ag);
                float h2 = sigm(ao) * tanhf(c2);
                *cptr = c2;
                Hw[(size_t)j * NW + s] = h2;
                if (last) d_Hfin[((size_t)dir * NW + s) * HID + j] = h2;
            }
        }
    }
}

// ---------------- gather output: out[w][dir*256+j] ----------------
__global__ void k_out(float* __restrict__ out) {
    int s = blockIdx.x;
    int tid = threadIdx.x;           // 512 threads: dir = tid>>8, j = tid&255
    int w = d_word_of_slot[s];
    int dir = tid >> 8, j = tid & 255;
    out[(size_t)w * 512 + tid] = d_Hfin[((size_t)dir * NW + s) * HID + j];
}

// ---------------- launch ----------------
extern "C" void kernel_launch(void* const* d_in, const int* in_sizes, int n_in,
                              void* d_out, int out_size) {
    const int*   char_ids = (const int*)d_in[0];
    const int*   lengths  = (const int*)d_in[1];
    const float* emb      = (const float*)d_in[2];
    const float* WihF = (const float*)d_in[3];
    const float* WhhF = (const float*)d_in[4];
    const float* bihF = (const float*)d_in[5];
    const float* bhhF = (const float*)d_in[6];
    const float* WihB = (const float*)d_in[7];
    const float* WhhB = (const float*)d_in[8];
    const float* bihB = (const float*)d_in[9];
    const float* bhhB = (const float*)d_in[10];
    float* out = (float*)d_out;

    k_init<<<1, 32>>>();
    k_wsplit<<<(2 * G4 * HID) / 256, 256>>>(WhhF, WhhB);
    k_ptable<<<dim3(VOCAB, 2), 256>>>(emb, WihF, bihF, bhhF, WihB, bihB, bhhB);
    k_hist<<<NW / 256, 256>>>(lengths);
    k_scan<<<1, 1>>>();
    k_scatter<<<NW / 256, 256>>>(lengths, char_ids);
    for (int t = 0; t < MAXLEN; t++)
        k_step<<<dim3(NW / 64, 8, 2), 256>>>(t);
    k_out<<<NW, 512>>>(out);
}

// round 5
// speedup vs baseline: 1.8992x; 1.2100x over previous
#include <cuda_runtime.h>
#include <cuda_bf16.h>
#include <cstdint>

#define NW     16384
#define MAXLEN 16
#define VOCAB  128
#define EMB    64
#define HID    256
#define G4     1024

// ---------------- static device state (no allocation) ----------------
__device__ float d_P[2 * VOCAB * G4];                 // char->gate table incl. biases
__device__ float d_C[(size_t)2 * NW * HID];           // c: [dir][slot][j]
__device__ float d_Hfin[(size_t)2 * NW * HID];        // final h: [dir][slot][j]
// H packed bf16 (hi | lo<<16): [buf][dir][k][slot]
__device__ uint32_t d_Hpk[(size_t)2 * 2 * HID * NW];
// W smem image: [dir][jb][chunk][sp][128 rows][pitch 40 bf16]
__device__ __align__(16) __nv_bfloat16 d_Wimg[(size_t)2 * 8 * 8 * 2 * 128 * 40];
__device__ int   d_hist[MAXLEN + 2];
__device__ int   d_cursor[MAXLEN + 2];
__device__ int   d_offset[MAXLEN + 2];
__device__ int   d_nactive[MAXLEN];
__device__ int   d_word_of_slot[NW];
__device__ unsigned char d_slot_len[NW];
__device__ unsigned char d_chars[2][MAXLEN][NW];

// ---------------- helpers ----------------
__device__ __forceinline__ float sigm(float x) {
    return __fdividef(1.f, 1.f + __expf(-x));
}
__device__ __forceinline__ void mma_bf16(float c[4], const uint32_t a[4],
                                         uint32_t b0, uint32_t b1) {
    asm volatile(
        "mma.sync.aligned.m16n8k16.row.col.f32.bf16.bf16.f32 "
        "{%0,%1,%2,%3}, {%4,%5,%6,%7}, {%8,%9}, {%0,%1,%2,%3};"
        : "+f"(c[0]), "+f"(c[1]), "+f"(c[2]), "+f"(c[3])
        : "r"(a[0]), "r"(a[1]), "r"(a[2]), "r"(a[3]), "r"(b0), "r"(b1));
}
__device__ __forceinline__ uint32_t smem_u32(const void* p) {
    uint32_t a;
    asm("{ .reg .u64 t; cvta.to.shared.u64 t, %1; cvt.u32.u64 %0, t; }" : "=r"(a) : "l"(p));
    return a;
}
__device__ __forceinline__ void cp16(uint32_t dst, const void* src) {
    asm volatile("cp.async.cg.shared.global [%0], [%1], 16;" :: "r"(dst), "l"(src) : "memory");
}
__device__ __forceinline__ void cp_commit() {
    asm volatile("cp.async.commit_group;" ::: "memory");
}
template <int N>
__device__ __forceinline__ void cp_wait() {
    asm volatile("cp.async.wait_group %0;" :: "n"(N) : "memory");
}

// ---------------- setup ----------------
__global__ void k_init() {
    int i = threadIdx.x;
    if (i <= MAXLEN + 1) { d_hist[i] = 0; d_cursor[i] = 0; }
}
__global__ void k_hist(const int* __restrict__ lengths) {
    int w = blockIdx.x * blockDim.x + threadIdx.x;
    if (w < NW) atomicAdd(&d_hist[lengths[w]], 1);
}
__global__ void k_scan() {
    int off = 0;
    for (int L = MAXLEN; L >= 1; L--) { d_offset[L] = off; off += d_hist[L]; }
    for (int t = 0; t < MAXLEN; t++) {
        int n = 0;
        for (int L = t + 1; L <= MAXLEN; L++) n += d_hist[L];
        d_nactive[t] = n;
    }
}
__global__ void k_scatter(const int* __restrict__ lengths, const int* __restrict__ char_ids) {
    int w = blockIdx.x * blockDim.x + threadIdx.x;
    if (w >= NW) return;
    int len = lengths[w];
    int pos = d_offset[len] + atomicAdd(&d_cursor[len], 1);
    d_word_of_slot[pos] = w;
    d_slot_len[pos] = (unsigned char)len;
#pragma unroll
    for (int t = 0; t < MAXLEN; t++) {
        d_chars[0][t][pos] = (unsigned char)char_ids[w * MAXLEN + t];
        int r = len - 1 - t; if (r < 0) r = 0;
        d_chars[1][t][pos] = (unsigned char)char_ids[w * MAXLEN + r];
    }
}
// W -> pre-pitched bf16 hi/lo smem image
__global__ void k_wsplit(const float* __restrict__ WhhF, const float* __restrict__ WhhB) {
    int i = blockIdx.x * blockDim.x + threadIdx.x;   // 2*1024*256
    int dir = i >> 18;
    int e = i & 0x3FFFF;
    int row = e >> 8, k = e & 255;
    int g = row >> 8, j = row & 255;
    int jb = j >> 5, jl = j & 31;
    int r128 = g * 32 + jl;
    int ch = k >> 5, kc = k & 31;
    float x = (dir ? WhhB : WhhF)[(size_t)row * 256 + k];
    __nv_bfloat16 hi = __float2bfloat16_rn(x);
    __nv_bfloat16 lo = __float2bfloat16_rn(x - __bfloat162float(hi));
    size_t b = (((size_t)((dir * 8 + jb) * 8 + ch) * 2) * 128 + r128) * 40 + kc;
    d_Wimg[b] = hi;
    d_Wimg[b + 5120] = lo;   // sp=1 plane
}
// P[d][v][row]
__global__ void k_ptable(const float* __restrict__ emb,
                         const float* __restrict__ WihF, const float* __restrict__ bihF,
                         const float* __restrict__ bhhF,
                         const float* __restrict__ WihB, const float* __restrict__ bihB,
                         const float* __restrict__ bhhB) {
    int v = blockIdx.x, d = blockIdx.y;
    const float* Wih = d ? WihB : WihF;
    const float* bih = d ? bihB : bihF;
    const float* bhh = d ? bhhB : bhhF;
    __shared__ float e[EMB];
    if (threadIdx.x < EMB) e[threadIdx.x] = emb[v * EMB + threadIdx.x];
    __syncthreads();
#pragma unroll
    for (int q = 0; q < 4; q++) {
        int j = threadIdx.x + q * 256;
        const float* wr = &Wih[j * EMB];
        float s = 0.f;
#pragma unroll
        for (int k = 0; k < EMB; k += 4) {
            float4 wv = *reinterpret_cast<const float4*>(&wr[k]);
            s += e[k] * wv.x + e[k + 1] * wv.y + e[k + 2] * wv.z + e[k + 3] * wv.w;
        }
        d_P[(d * VOCAB + v) * G4 + j] = s + bih[j] + bhh[j];
    }
}

// ---------------- fused recurrent step ----------------
// Block: 128 slots x 32 j x 4 gates, 8 warps (ws 0-3: 32 slots, wj 0-1: 16 j).
// A tile: packed uint32 [32 k][pitch 132] per buffer. W tile: bf16 [sp][128][pitch 40].
#define AS_PITCH 132
#define AS_BYTES (32 * AS_PITCH * 4)          // 16896
#define WS_BYTES (2 * 128 * 40 * 2)           // 20480
#define SM_WS0   (2 * AS_BYTES)               // 33792
#define SM_TOT   (SM_WS0 + 2 * WS_BYTES)      // 74752

__global__ void __launch_bounds__(256, 2) k_step(int t) {
    const int nact = d_nactive[t];
    const int slot0 = blockIdx.x * 128;
    if (slot0 >= nact) return;
    const int jb = blockIdx.y, j0 = jb * 32;
    const int dir = blockIdx.z;
    const int rb = t & 1, wb = rb ^ 1;

    extern __shared__ __align__(16) char smem[];
    const uint32_t sb = smem_u32(smem);
    const uint32_t* __restrict__ Hpk = d_Hpk + (size_t)(rb * 2 + dir) * HID * NW;
    const char* wimg = (const char*)d_Wimg + (size_t)(dir * 8 + jb) * 8 * 2 * 10240;

    const int tid = threadIdx.x;
    const int warp = tid >> 5, lane = tid & 31;
    const int ws = warp & 3, wj = warp >> 2;
    const int g4 = lane >> 2, t4 = lane & 3;

    float acc[4][2][2][4];
#pragma unroll
    for (int g = 0; g < 4; g++)
#pragma unroll
        for (int nh = 0; nh < 2; nh++)
#pragma unroll
            for (int mh = 0; mh < 2; mh++)
#pragma unroll
                for (int r = 0; r < 4; r++) acc[g][nh][mh][r] = 0.f;

    if (t > 0) {
        // ---- cp.async staging helper ----
        auto issue_chunk = [&](int c, int buf) {
            uint32_t asB = sb + buf * AS_BYTES;
            uint32_t wsB = sb + SM_WS0 + buf * WS_BYTES;
            const char* wsrc = wimg + c * 2 * 10240;
#pragma unroll 1
            for (int u = tid; u < 2304; u += 256) {
                if (u < 1024) {
                    int k = u >> 5, o = u & 31;
                    cp16(asB + k * (AS_PITCH * 4) + o * 16,
                         (const char*)(Hpk + (size_t)(c * 32 + k) * NW + slot0) + o * 16);
                } else {
                    int w = u - 1024;
                    int sp = (w >= 640) ? 1 : 0;
                    int r = w - sp * 640;
                    cp16(wsB + sp * 10240 + r * 16, wsrc + sp * 10240 + r * 16);
                }
            }
        };

        issue_chunk(0, 0); cp_commit();
        issue_chunk(1, 1); cp_commit();

#pragma unroll 1
        for (int c = 0; c < 8; c++) {
            if (c < 7) cp_wait<1>(); else cp_wait<0>();
            __syncthreads();
            const int buf = c & 1;
            const uint32_t* As = (const uint32_t*)(smem + buf * AS_BYTES);
            const __nv_bfloat16* Wsm = (const __nv_bfloat16*)(smem + SM_WS0 + buf * WS_BYTES);
#pragma unroll
            for (int kk = 0; kk < 32; kk += 16) {
                uint32_t ah[2][4], al[2][4];
#pragma unroll
                for (int mh = 0; mh < 2; mh++) {
                    int s0 = ws * 32 + mh * 16 + g4;
#pragma unroll
                    for (int kh = 0; kh < 2; kh++) {
#pragma unroll
                        for (int rh = 0; rh < 2; rh++) {
                            int kl = kk + kh * 8 + 2 * t4;
                            uint32_t w0 = As[kl * AS_PITCH + s0 + rh * 8];
                            uint32_t w1 = As[(kl + 1) * AS_PITCH + s0 + rh * 8];
                            int idx = kh * 2 + rh;
                            ah[mh][idx] = __byte_perm(w0, w1, 0x5410);
                            al[mh][idx] = __byte_perm(w0, w1, 0x7632);
                        }
                    }
                }
#pragma unroll
                for (int g = 0; g < 4; g++) {
#pragma unroll
                    for (int nh = 0; nh < 2; nh++) {
                        int br = (g * 32 + wj * 16 + nh * 8 + g4) * 40 + kk + 2 * t4;
                        uint32_t bh0 = *reinterpret_cast<const uint32_t*>(&Wsm[br]);
                        uint32_t bh1 = *reinterpret_cast<const uint32_t*>(&Wsm[br + 8]);
                        uint32_t bl0 = *reinterpret_cast<const uint32_t*>(&Wsm[br + 5120]);
                        uint32_t bl1 = *reinterpret_cast<const uint32_t*>(&Wsm[br + 5128]);
#pragma unroll
                        for (int mh = 0; mh < 2; mh++) {
                            mma_bf16(acc[g][nh][mh], ah[mh], bh0, bh1);
                            mma_bf16(acc[g][nh][mh], ah[mh], bl0, bl1);
                            mma_bf16(acc[g][nh][mh], al[mh], bh0, bh1);
                        }
                    }
                }
            }
            __syncthreads();
            if (c + 2 < 8) { issue_chunk(c + 2, buf); cp_commit(); }
        }
    }

    // ---- epilogue: LSTM cell, all 4 gates thread-local ----
    uint32_t* HpkW = d_Hpk + (size_t)(wb * 2 + dir) * HID * NW;
#pragma unroll
    for (int mh = 0; mh < 2; mh++) {
#pragma unroll
        for (int rh = 0; rh < 2; rh++) {
            int s = slot0 + ws * 32 + mh * 16 + rh * 8 + g4;
            if (s >= nact) continue;
            int v = d_chars[dir][t][s];
            const float* Pv = &d_P[((dir << 7) + v) << 10];
            bool last = (t == (int)d_slot_len[s] - 1);
            float* crow = &d_C[((size_t)dir * NW + s) * HID];
            float* frow = &d_Hfin[((size_t)dir * NW + s) * HID];
#pragma unroll
            for (int nh = 0; nh < 2; nh++) {
#pragma unroll
                for (int cp = 0; cp < 2; cp++) {
                    int j = j0 + wj * 16 + nh * 8 + 2 * t4 + cp;
                    float a = acc[0][nh][mh][rh * 2 + cp];
                    float f = acc[1][nh][mh][rh * 2 + cp];
                    float gg = acc[2][nh][mh][rh * 2 + cp];
                    float o = acc[3][nh][mh][rh * 2 + cp];
                    float ai = a + Pv[j];
                    float af = f + Pv[256 + j];
                    float ag = gg + Pv[512 + j];
                    float ao = o + Pv[768 + j];
                    float cprev = (t == 0) ? 0.f : crow[j];
                    float c2 = sigm(af) * cprev + sigm(ai) * tanhf(ag);
                    float h2 = sigm(ao) * tanhf(c2);
                    crow[j] = c2;
                    if (last) frow[j] = h2;
                    __nv_bfloat16 hi = __float2bfloat16_rn(h2);
                    __nv_bfloat16 lo = __float2bfloat16_rn(h2 - __bfloat162float(hi));
                    uint32_t pk = (uint32_t)*reinterpret_cast<unsigned short*>(&hi)
                                | ((uint32_t)*reinterpret_cast<unsigned short*>(&lo) << 16);
                    HpkW[(size_t)j * NW + s] = pk;
                }
            }
        }
    }
}

// ---------------- gather output ----------------
__global__ void k_out(float* __restrict__ out) {
    int s = blockIdx.x;
    int tid = threadIdx.x;
    int w = d_word_of_slot[s];
    int dir = tid >> 8, j = tid & 255;
    out[(size_t)w * 512 + tid] = d_Hfin[((size_t)dir * NW + s) * HID + j];
}

// ---------------- launch ----------------
extern "C" void kernel_launch(void* const* d_in, const int* in_sizes, int n_in,
                              void* d_out, int out_size) {
    const int*   char_ids = (const int*)d_in[0];
    const int*   lengths  = (const int*)d_in[1];
    const float* emb      = (const float*)d_in[2];
    const float* WihF = (const float*)d_in[3];
    const float* WhhF = (const float*)d_in[4];
    const float* bihF = (const float*)d_in[5];
    const float* bhhF = (const float*)d_in[6];
    const float* WihB = (const float*)d_in[7];
    const float* WhhB = (const float*)d_in[8];
    const float* bihB = (const float*)d_in[9];
    const float* bhhB = (const float*)d_in[10];
    float* out = (float*)d_out;

    static bool s_init = false;
    if (!s_init) {
        cudaFuncSetAttribute(k_step, cudaFuncAttributeMaxDynamicSharedMemorySize, SM_TOT);
        s_init = true;
    }

    k_init<<<1, 32>>>();
    k_wsplit<<<2048, 256>>>(WhhF, WhhB);
    k_ptable<<<dim3(VOCAB, 2), 256>>>(emb, WihF, bihF, bhhF, WihB, bihB, bhhB);
    k_hist<<<NW / 256, 256>>>(lengths);
    k_scan<<<1, 1>>>();
    k_scatter<<<NW / 256, 256>>>(lengths, char_ids);
    for (int t = 0; t < MAXLEN; t++)
        k_step<<<dim3(NW / 128, 8, 2), 256, SM_TOT>>>(t);
    k_out<<<NW, 512>>>(out);
}

// round 6
// speedup vs baseline: 2.0076x; 1.0571x over previous
#include <cuda_runtime.h>
#include <cuda_fp16.h>
#include <cstdint>

#define NW     16384
#define MAXLEN 16
#define VOCAB  128
#define EMB    64
#define HID    256
#define G4     1024

// ---------------- static device state (no allocation) ----------------
__device__ float d_P[2 * VOCAB * G4];                 // char->gate table incl. biases
__device__ float d_C[(size_t)2 * NW * HID];           // c: [dir][slot][j]
__device__ float d_Hfin[(size_t)2 * NW * HID];        // final h: [dir][slot][j]
// H packed fp16 (hi | lo<<16): [buf][dir][k][slot]
__device__ uint32_t d_Hpk[(size_t)2 * 2 * HID * NW];
// W smem image (single fp16 plane): [dir][jb][chunk][128 rows][pitch 40]
__device__ __align__(16) __half d_Wimg[(size_t)2 * 8 * 8 * 128 * 40];
__device__ int   d_cursor[MAXLEN + 2];
__device__ int   d_offset[MAXLEN + 2];
__device__ int   d_nactive[MAXLEN];
__device__ int   d_word_of_slot[NW];
__device__ unsigned char d_slot_len[NW];
__device__ unsigned char d_chars[2][MAXLEN][NW];

// ---------------- helpers ----------------
__device__ __forceinline__ float sigm(float x) {
    return __fdividef(1.f, 1.f + __expf(-x));
}
__device__ __forceinline__ void mma_f16(float c[4], const uint32_t a[4],
                                        uint32_t b0, uint32_t b1) {
    asm volatile(
        "mma.sync.aligned.m16n8k16.row.col.f32.f16.f16.f32 "
        "{%0,%1,%2,%3}, {%4,%5,%6,%7}, {%8,%9}, {%0,%1,%2,%3};"
        : "+f"(c[0]), "+f"(c[1]), "+f"(c[2]), "+f"(c[3])
        : "r"(a[0]), "r"(a[1]), "r"(a[2]), "r"(a[3]), "r"(b0), "r"(b1));
}
__device__ __forceinline__ uint32_t smem_u32(const void* p) {
    uint32_t a;
    asm("{ .reg .u64 t; cvta.to.shared.u64 t, %1; cvt.u32.u64 %0, t; }" : "=r"(a) : "l"(p));
    return a;
}
__device__ __forceinline__ void cp16(uint32_t dst, const void* src) {
    asm volatile("cp.async.cg.shared.global [%0], [%1], 16;" :: "r"(dst), "l"(src) : "memory");
}
__device__ __forceinline__ void cp_commit() {
    asm volatile("cp.async.commit_group;" ::: "memory");
}
template <int N>
__device__ __forceinline__ void cp_wait() {
    asm volatile("cp.async.wait_group %0;" :: "n"(N) : "memory");
}
__device__ __forceinline__ uint32_t pack_h(float h) {
    __half hi = __float2half_rn(h);
    __half lo = __float2half_rn(h - __half2float(hi));
    return (uint32_t)__half_as_ushort(hi) | ((uint32_t)__half_as_ushort(lo) << 16);
}

// ---------------- setup: hist + scan + cursor (one block) ----------------
__global__ void k_setup(const int* __restrict__ lengths) {
    __shared__ int sh[MAXLEN + 2];
    int tid = threadIdx.x;                      // 1024
    if (tid <= MAXLEN + 1) sh[tid] = 0;
    __syncthreads();
    for (int w = tid; w < NW; w += 1024) atomicAdd(&sh[lengths[w]], 1);
    __syncthreads();
    if (tid == 0) {
        int off = 0;
        for (int L = MAXLEN; L >= 1; L--) { d_offset[L] = off; off += sh[L]; }
        for (int t = 0; t < MAXLEN; t++) {
            int n = 0;
            for (int L = t + 1; L <= MAXLEN; L++) n += sh[L];
            d_nactive[t] = n;
        }
    }
    if (tid <= MAXLEN + 1) d_cursor[tid] = 0;
}

// ---------------- prep: W image + P table, fused ----------------
__global__ void k_prep(const float* __restrict__ emb,
                       const float* __restrict__ WihF, const float* __restrict__ bihF,
                       const float* __restrict__ bhhF,
                       const float* __restrict__ WihB, const float* __restrict__ bihB,
                       const float* __restrict__ bhhB,
                       const float* __restrict__ WhhF, const float* __restrict__ WhhB) {
    if (blockIdx.x < 2048) {
        // W -> fp16 pre-pitched smem image
        int i = blockIdx.x * 256 + threadIdx.x;    // 2*1024*256
        int dir = i >> 18;
        int e = i & 0x3FFFF;
        int row = e >> 8, k = e & 255;
        int g = row >> 8, j = row & 255;
        int jb = j >> 5, jl = j & 31;
        int r128 = g * 32 + jl;
        int ch = k >> 5, kc = k & 31;
        float x = (dir ? WhhB : WhhF)[(size_t)row * 256 + k];
        d_Wimg[((size_t)((dir * 8 + jb) * 8 + ch) * 128 + r128) * 40 + kc] = __float2half_rn(x);
    } else {
        int bid = blockIdx.x - 2048;
        int v = bid & 127, d = bid >> 7;
        const float* Wih = d ? WihB : WihF;
        const float* bih = d ? bihB : bihF;
        const float* bhh = d ? bhhB : bhhF;
        __shared__ float esm[EMB];
        if (threadIdx.x < EMB) esm[threadIdx.x] = emb[v * EMB + threadIdx.x];
        __syncthreads();
#pragma unroll
        for (int q = 0; q < 4; q++) {
            int j = threadIdx.x + q * 256;
            const float* wr = &Wih[j * EMB];
            float s = 0.f;
#pragma unroll
            for (int k = 0; k < EMB; k += 4) {
                float4 wv = *reinterpret_cast<const float4*>(&wr[k]);
                s += esm[k] * wv.x + esm[k + 1] * wv.y + esm[k + 2] * wv.z + esm[k + 3] * wv.w;
            }
            d_P[(d * VOCAB + v) * G4 + j] = s + bih[j] + bhh[j];
        }
    }
}

// ---------------- scatter + step 0 (h0 = 0 -> gates = P[char]) ----------------
__global__ void __launch_bounds__(512)
k_scatter0(const int* __restrict__ lengths, const int* __restrict__ char_ids) {
    int tid = threadIdx.x;
    int wloc = tid >> 3, sub = tid & 7;
    int w = blockIdx.x * 64 + wloc;
    __shared__ int spos[64];
    int len = lengths[w];
    if (sub == 0) {
        int pos = d_offset[len] + atomicAdd(&d_cursor[len], 1);
        spos[wloc] = pos;
        d_word_of_slot[pos] = w;
        d_slot_len[pos] = (unsigned char)len;
#pragma unroll
        for (int t = 0; t < MAXLEN; t++) {
            d_chars[0][t][pos] = (unsigned char)char_ids[w * MAXLEN + t];
            int r = len - 1 - t; if (r < 0) r = 0;
            d_chars[1][t][pos] = (unsigned char)char_ids[w * MAXLEN + r];
        }
    }
    __syncthreads();
    int pos = spos[wloc];
    int dir = sub >> 2;
    int j0 = (sub & 3) * 64;
    int v = char_ids[w * MAXLEN + (dir ? (len - 1) : 0)];
    const float* Pv = &d_P[((dir << 7) + v) << 10];
    bool last = (len == 1);
    float* crow = &d_C[((size_t)dir * NW + pos) * HID];
    float* frow = &d_Hfin[((size_t)dir * NW + pos) * HID];
    uint32_t* hrow = d_Hpk + (size_t)(2 + dir) * HID * NW;   // buf 1
#pragma unroll 4
    for (int q = 0; q < 64; q++) {
        int j = j0 + q;
        float c1 = sigm(Pv[j]) * tanhf(Pv[512 + j]);
        float h1 = sigm(Pv[768 + j]) * tanhf(c1);
        crow[j] = c1;
        hrow[(size_t)j * NW + pos] = pack_h(h1);
        if (last) frow[j] = h1;
    }
}

// ---------------- fused recurrent step (t >= 1) ----------------
// Block: 128 slots x 32 j x 4 gates, 8 warps (ws 0-3: 32 slots, wj 0-1: 16 j).
#define AS_PITCH 132
#define AS_BYTES (32 * AS_PITCH * 4)          // 16896
#define WS_BYTES (128 * 40 * 2)               // 10240
#define SM_WS0   (2 * AS_BYTES)               // 33792
#define SM_TOT   (SM_WS0 + 2 * WS_BYTES)      // 54272

__global__ void __launch_bounds__(256, 2) k_step(int t) {
    const int nact = d_nactive[t];
    const int slot0 = blockIdx.x * 128;
    if (slot0 >= nact) return;
    const int jb = blockIdx.y, j0 = jb * 32;
    const int dir = blockIdx.z;
    const int rb = t & 1, wb = rb ^ 1;

    extern __shared__ __align__(16) char smem[];
    const uint32_t sb = smem_u32(smem);
    const uint32_t* __restrict__ Hpk = d_Hpk + (size_t)(rb * 2 + dir) * HID * NW;
    const char* wimg = (const char*)d_Wimg + (size_t)(dir * 8 + jb) * 8 * 10240;

    const int tid = threadIdx.x;
    const int warp = tid >> 5, lane = tid & 31;
    const int ws = warp & 3, wj = warp >> 2;
    const int g4 = lane >> 2, t4 = lane & 3;

    float acc[4][2][2][4];
#pragma unroll
    for (int g = 0; g < 4; g++)
#pragma unroll
        for (int nh = 0; nh < 2; nh++)
#pragma unroll
            for (int mh = 0; mh < 2; mh++)
#pragma unroll
                for (int r = 0; r < 4; r++) acc[g][nh][mh][r] = 0.f;

    auto issue_chunk = [&](int c, int buf) {
        uint32_t asB = sb + buf * AS_BYTES;
        uint32_t wsB = sb + SM_WS0 + buf * WS_BYTES;
        const char* wsrc = wimg + c * 10240;
#pragma unroll 1
        for (int u = tid; u < 1664; u += 256) {
            if (u < 1024) {
                int k = u >> 5, o = u & 31;
                cp16(asB + k * (AS_PITCH * 4) + o * 16,
                     (const char*)(Hpk + (size_t)(c * 32 + k) * NW + slot0) + o * 16);
            } else {
                int r = u - 1024;
                cp16(wsB + r * 16, wsrc + r * 16);
            }
        }
    };

    issue_chunk(0, 0); cp_commit();
    issue_chunk(1, 1); cp_commit();

#pragma unroll 1
    for (int c = 0; c < 8; c++) {
        if (c < 7) cp_wait<1>(); else cp_wait<0>();
        __syncthreads();
        const int buf = c & 1;
        const uint32_t* As = (const uint32_t*)(smem + buf * AS_BYTES);
        const __half* Wsm = (const __half*)(smem + SM_WS0 + buf * WS_BYTES);
#pragma unroll
        for (int kk = 0; kk < 32; kk += 16) {
            uint32_t ah[2][4], al[2][4];
#pragma unroll
            for (int mh = 0; mh < 2; mh++) {
                int s0 = ws * 32 + mh * 16 + g4;
#pragma unroll
                for (int kh = 0; kh < 2; kh++) {
#pragma unroll
                    for (int rh = 0; rh < 2; rh++) {
                        int kl = kk + kh * 8 + 2 * t4;
                        uint32_t w0 = As[kl * AS_PITCH + s0 + rh * 8];
                        uint32_t w1 = As[(kl + 1) * AS_PITCH + s0 + rh * 8];
                        int idx = kh * 2 + rh;
                        ah[mh][idx] = __byte_perm(w0, w1, 0x5410);
                        al[mh][idx] = __byte_perm(w0, w1, 0x7632);
                    }
                }
            }
#pragma unroll
            for (int g = 0; g < 4; g++) {
#pragma unroll
                for (int nh = 0; nh < 2; nh++) {
                    int br = (g * 32 + wj * 16 + nh * 8 + g4) * 40 + kk + 2 * t4;
                    uint32_t b0 = *reinterpret_cast<const uint32_t*>(&Wsm[br]);
                    uint32_t b1 = *reinterpret_cast<const uint32_t*>(&Wsm[br + 8]);
#pragma unroll
                    for (int mh = 0; mh < 2; mh++) {
                        mma_f16(acc[g][nh][mh], ah[mh], b0, b1);
                        mma_f16(acc[g][nh][mh], al[mh], b0, b1);
                    }
                }
            }
        }
        __syncthreads();
        if (c + 2 < 8) { issue_chunk(c + 2, buf); cp_commit(); }
    }

    // ---- epilogue: LSTM cell, all 4 gates thread-local ----
    uint32_t* HpkW = d_Hpk + (size_t)(wb * 2 + dir) * HID * NW;
#pragma unroll
    for (int mh = 0; mh < 2; mh++) {
#pragma unroll
        for (int rh = 0; rh < 2; rh++) {
            int s = slot0 + ws * 32 + mh * 16 + rh * 8 + g4;
            if (s >= nact) continue;
            int v = d_chars[dir][t][s];
            const float* Pv = &d_P[((dir << 7) + v) << 10];
            bool last = (t == (int)d_slot_len[s] - 1);
            float* crow = &d_C[((size_t)dir * NW + s) * HID];
            float* frow = &d_Hfin[((size_t)dir * NW + s) * HID];
#pragma unroll
            for (int nh = 0; nh < 2; nh++) {
#pragma unroll
                for (int cp = 0; cp < 2; cp++) {
                    int j = j0 + wj * 16 + nh * 8 + 2 * t4 + cp;
                    float ai = acc[0][nh][mh][rh * 2 + cp] + Pv[j];
                    float af = acc[1][nh][mh][rh * 2 + cp] + Pv[256 + j];
                    float ag = acc[2][nh][mh][rh * 2 + cp] + Pv[512 + j];
                    float ao = acc[3][nh][mh][rh * 2 + cp] + Pv[768 + j];
                    float c2 = sigm(af) * crow[j] + sigm(ai) * tanhf(ag);
                    float h2 = sigm(ao) * tanhf(c2);
                    crow[j] = c2;
                    if (last) frow[j] = h2;
                    HpkW[(size_t)j * NW + s] = pack_h(h2);
                }
            }
        }
    }
}

// ---------------- gather output ----------------
__global__ void k_out(float* __restrict__ out) {
    int s = blockIdx.x;
    int tid = threadIdx.x;
    int w = d_word_of_slot[s];
    int dir = tid >> 8, j = tid & 255;
    out[(size_t)w * 512 + tid] = d_Hfin[((size_t)dir * NW + s) * HID + j];
}

// ---------------- launch ----------------
extern "C" void kernel_launch(void* const* d_in, const int* in_sizes, int n_in,
                              void* d_out, int out_size) {
    const int*   char_ids = (const int*)d_in[0];
    const int*   lengths  = (const int*)d_in[1];
    const float* emb      = (const float*)d_in[2];
    const float* WihF = (const float*)d_in[3];
    const float* WhhF = (const float*)d_in[4];
    const float* bihF = (const float*)d_in[5];
    const float* bhhF = (const float*)d_in[6];
    const float* WihB = (const float*)d_in[7];
    const float* WhhB = (const float*)d_in[8];
    const float* bihB = (const float*)d_in[9];
    const float* bhhB = (const float*)d_in[10];
    float* out = (float*)d_out;

    static bool s_init = false;
    if (!s_init) {
        cudaFuncSetAttribute(k_step, cudaFuncAttributeMaxDynamicSharedMemorySize, SM_TOT);
        s_init = true;
    }

    k_setup<<<1, 1024>>>(lengths);
    k_prep<<<2048 + 256, 256>>>(emb, WihF, bihF, bhhF, WihB, bihB, bhhB, WhhF, WhhB);
    k_scatter0<<<NW / 64, 512>>>(lengths, char_ids);
    for (int t = 1; t < MAXLEN; t++)
        k_step<<<dim3(NW / 128, 8, 2), 256, SM_TOT>>>(t);
    k_out<<<NW, 512>>>(out);
}

// round 8
// speedup vs baseline: 2.1786x; 1.0852x over previous
#include <cuda_runtime.h>
#include <cuda_fp16.h>
#include <cstdint>

#define NW     16384
#define MAXLEN 16
#define VOCAB  128
#define EMB    64
#define HID    256
#define G4     1024

// ---------------- static device state (no allocation) ----------------
__device__ float d_P[2 * VOCAB * G4];                 // char->gate table incl. biases
__device__ float d_C[(size_t)2 * NW * HID];           // c: [dir][slot][j]
__device__ float d_Hfin[(size_t)2 * NW * HID];        // final h: [dir][slot][j]
// H fp16: [buf][dir][slot][k]
__device__ __align__(16) __half d_Hh[(size_t)2 * 2 * NW * HID];
// W smem image fp16: [dir][jb][chunk(4)][128 rows][pitch 72]
__device__ __align__(16) __half d_Wimg[(size_t)2 * 8 * 4 * 128 * 72];
__device__ int   d_cursor[MAXLEN + 2];
__device__ int   d_offset[MAXLEN + 2];
__device__ int   d_nactive[MAXLEN];
__device__ int   d_word_of_slot[NW];
__device__ unsigned char d_slot_len[NW];
__device__ unsigned char d_chars[2][MAXLEN][NW];

// ---------------- helpers ----------------
__device__ __forceinline__ float sigm(float x) {
    return __fdividef(1.f, 1.f + __expf(-x));
}
__device__ __forceinline__ void mma_f16(float c[4], const uint32_t a[4],
                                        uint32_t b0, uint32_t b1) {
    asm volatile(
        "mma.sync.aligned.m16n8k16.row.col.f32.f16.f16.f32 "
        "{%0,%1,%2,%3}, {%4,%5,%6,%7}, {%8,%9}, {%0,%1,%2,%3};"
        : "+f"(c[0]), "+f"(c[1]), "+f"(c[2]), "+f"(c[3])
        : "r"(a[0]), "r"(a[1]), "r"(a[2]), "r"(a[3]), "r"(b0), "r"(b1));
}
__device__ __forceinline__ uint32_t smem_u32(const void* p) {
    uint32_t a;
    asm("{ .reg .u64 t; cvta.to.shared.u64 t, %1; cvt.u32.u64 %0, t; }" : "=r"(a) : "l"(p));
    return a;
}
__device__ __forceinline__ void cp16(uint32_t dst, const void* src) {
    asm volatile("cp.async.cg.shared.global [%0], [%1], 16;" :: "r"(dst), "l"(src) : "memory");
}
__device__ __forceinline__ void cp_commit() {
    asm volatile("cp.async.commit_group;" ::: "memory");
}
template <int N>
__device__ __forceinline__ void cp_wait() {
    asm volatile("cp.async.wait_group %0;" :: "n"(N) : "memory");
}

// ---------------- setup: hist + scan + cursor (one block) ----------------
__global__ void k_setup(const int* __restrict__ lengths) {
    __shared__ int sh[MAXLEN + 2];
    int tid = threadIdx.x;                      // 1024
    if (tid <= MAXLEN + 1) sh[tid] = 0;
    __syncthreads();
    for (int w = tid; w < NW; w += 1024) atomicAdd(&sh[lengths[w]], 1);
    __syncthreads();
    if (tid == 0) {
        int off = 0;
        for (int L = MAXLEN; L >= 1; L--) { d_offset[L] = off; off += sh[L]; }
        for (int t = 0; t < MAXLEN; t++) {
            int n = 0;
            for (int L = t + 1; L <= MAXLEN; L++) n += sh[L];
            d_nactive[t] = n;
        }
    }
    if (tid <= MAXLEN + 1) d_cursor[tid] = 0;
}

// ---------------- prep: W image + P table, fused ----------------
__global__ void k_prep(const float* __restrict__ emb,
                       const float* __restrict__ WihF, const float* __restrict__ bihF,
                       const float* __restrict__ bhhF,
                       const float* __restrict__ WihB, const float* __restrict__ bihB,
                       const float* __restrict__ bhhB,
                       const float* __restrict__ WhhF, const float* __restrict__ WhhB) {
    if (blockIdx.x < 2048) {
        int i = blockIdx.x * 256 + threadIdx.x;    // 2*1024*256
        int dir = i >> 18;
        int e = i & 0x3FFFF;
        int row = e >> 8, k = e & 255;
        int g = row >> 8, j = row & 255;
        int jb = j >> 5, jl = j & 31;
        int r128 = g * 32 + jl;
        int ch = k >> 6, kc = k & 63;
        float x = (dir ? WhhB : WhhF)[(size_t)row * 256 + k];
        d_Wimg[((size_t)((dir * 8 + jb) * 4 + ch) * 128 + r128) * 72 + kc] = __float2half_rn(x);
    } else {
        int bid = blockIdx.x - 2048;
        int v = bid & 127, d = bid >> 7;
        const float* Wih = d ? WihB : WihF;
        const float* bih = d ? bihB : bihF;
        const float* bhh = d ? bhhB : bhhF;
        __shared__ float esm[EMB];
        if (threadIdx.x < EMB) esm[threadIdx.x] = emb[v * EMB + threadIdx.x];
        __syncthreads();
#pragma unroll
        for (int q = 0; q < 4; q++) {
            int j = threadIdx.x + q * 256;
            const float* wr = &Wih[j * EMB];
            float s = 0.f;
#pragma unroll
            for (int k = 0; k < EMB; k += 4) {
                float4 wv = *reinterpret_cast<const float4*>(&wr[k]);
                s += esm[k] * wv.x + esm[k + 1] * wv.y + esm[k + 2] * wv.z + esm[k + 3] * wv.w;
            }
            d_P[(d * VOCAB + v) * G4 + j] = s + bih[j] + bhh[j];
        }
    }
}

// ---------------- scatter + step 0 (h0 = 0 -> gates = P[char]) ----------------
__global__ void __launch_bounds__(512)
k_scatter0(const int* __restrict__ lengths, const int* __restrict__ char_ids) {
    int tid = threadIdx.x;
    int wloc = tid >> 3, sub = tid & 7;
    int w = blockIdx.x * 64 + wloc;
    __shared__ int spos[64];
    int len = lengths[w];
    if (sub == 0) {
        int pos = d_offset[len] + atomicAdd(&d_cursor[len], 1);
        spos[wloc] = pos;
        d_word_of_slot[pos] = w;
        d_slot_len[pos] = (unsigned char)len;
#pragma unroll
        for (int t = 0; t < MAXLEN; t++) {
            d_chars[0][t][pos] = (unsigned char)char_ids[w * MAXLEN + t];
            int r = len - 1 - t; if (r < 0) r = 0;
            d_chars[1][t][pos] = (unsigned char)char_ids[w * MAXLEN + r];
        }
    }
    __syncthreads();
    int pos = spos[wloc];
    int dir = sub >> 2;
    int j0 = (sub & 3) * 64;
    int v = char_ids[w * MAXLEN + (dir ? (len - 1) : 0)];
    const float* Pv = &d_P[((dir << 7) + v) << 10];
    bool last = (len == 1);
    float* crow = &d_C[((size_t)dir * NW + pos) * HID];
    float* frow = &d_Hfin[((size_t)dir * NW + pos) * HID];
    __half* hrow = d_Hh + ((size_t)(2 + dir) * NW + pos) * HID;   // buf 1
#pragma unroll 2
    for (int q = 0; q < 64; q += 2) {
        float hv[2];
#pragma unroll
        for (int u = 0; u < 2; u++) {
            int j = j0 + q + u;
            float c1 = sigm(Pv[j]) * tanhf(Pv[512 + j]);
            float h1 = sigm(Pv[768 + j]) * tanhf(c1);
            crow[j] = c1;
            if (last) frow[j] = h1;
            hv[u] = h1;
        }
        __half2 h2v; h2v.x = __float2half_rn(hv[0]); h2v.y = __float2half_rn(hv[1]);
        *reinterpret_cast<__half2*>(&hrow[j0 + q]) = h2v;
    }
}

// ---------------- fused recurrent step (t >= 1) ----------------
// Block: 128 slots x 32 j x 4 gates, 8 warps (ws 0-3: 32 slots, wj 0-1: 16 j).
// A tile: fp16 [128 slot][pitch 72], W tile: fp16 [128 row][pitch 72], 64-k chunks.
#define AP        72
#define TILE_B    (128 * AP * 2)              // 18432
#define SM_WS0    (2 * TILE_B)                // 36864
#define SM_TOT    (SM_WS0 + 2 * TILE_B)       // 73728
#define W_SEGS    (TILE_B / 16)               // 1152

__global__ void __launch_bounds__(256, 2) k_step(int t) {
    const int nact = d_nactive[t];
    const int slot0 = blockIdx.x * 128;
    if (slot0 >= nact) return;
    const int jb = blockIdx.y, j0 = jb * 32;
    const int dir = blockIdx.z;
    const int rb = t & 1, wb = rb ^ 1;

    extern __shared__ __align__(16) char smem[];
    const uint32_t sb = smem_u32(smem);
    const __half* __restrict__ Hr = d_Hh + (size_t)(rb * 2 + dir) * NW * HID;
    const char* wimg = (const char*)d_Wimg + (size_t)(dir * 8 + jb) * 4 * TILE_B;

    const int tid = threadIdx.x;
    const int warp = tid >> 5, lane = tid & 31;
    const int ws = warp & 3, wj = warp >> 2;
    const int g4 = lane >> 2, t4 = lane & 3;

    float acc[4][2][2][4];
#pragma unroll
    for (int g = 0; g < 4; g++)
#pragma unroll
        for (int nh = 0; nh < 2; nh++)
#pragma unroll
            for (int mh = 0; mh < 2; mh++)
#pragma unroll
                for (int r = 0; r < 4; r++) acc[g][nh][mh][r] = 0.f;

    auto issue_chunk = [&](int c, int buf) {
        uint32_t asB = sb + buf * TILE_B;
        uint32_t wsB = sb + SM_WS0 + buf * TILE_B;
        const char* wsrc = wimg + c * TILE_B;
        // A: 1024 segs (128 slots x 8), W: full 1152 segs (18432 B incl. pad)
#pragma unroll 1
        for (int u = tid; u < 1024 + W_SEGS; u += 256) {
            if (u < 1024) {
                int s = u >> 3, ko = u & 7;
                cp16(asB + s * 144 + ko * 16,
                     (const char*)(Hr + (size_t)(slot0 + s) * HID) + c * 128 + ko * 16);
            } else {
                int r = u - 1024;
                cp16(wsB + r * 16, wsrc + r * 16);
            }
        }
    };

    issue_chunk(0, 0); cp_commit();
    issue_chunk(1, 1); cp_commit();

#pragma unroll 1
    for (int c = 0; c < 4; c++) {
        if (c < 3) cp_wait<1>(); else cp_wait<0>();
        __syncthreads();
        const int buf = c & 1;
        const uint32_t* As = (const uint32_t*)(smem + buf * TILE_B);
        const uint32_t* Ws = (const uint32_t*)(smem + SM_WS0 + buf * TILE_B);
#pragma unroll
        for (int kk = 0; kk < 64; kk += 16) {
            const int kw = (kk >> 1) + t4;
            uint32_t a[2][4];
#pragma unroll
            for (int mh = 0; mh < 2; mh++) {
                int s0 = ws * 32 + mh * 16 + g4;
                a[mh][0] = As[s0 * 36 + kw];
                a[mh][1] = As[(s0 + 8) * 36 + kw];
                a[mh][2] = As[s0 * 36 + kw + 4];
                a[mh][3] = As[(s0 + 8) * 36 + kw + 4];
            }
#pragma unroll
            for (int g = 0; g < 4; g++) {
#pragma unroll
                for (int nh = 0; nh < 2; nh++) {
                    int br = (g * 32 + wj * 16 + nh * 8 + g4) * 36 + kw;
                    uint32_t b0 = Ws[br];
                    uint32_t b1 = Ws[br + 4];
#pragma unroll
                    for (int mh = 0; mh < 2; mh++)
                        mma_f16(acc[g][nh][mh], a[mh], b0, b1);
                }
            }
        }
        __syncthreads();
        if (c + 2 < 4) { issue_chunk(c + 2, buf); cp_commit(); }
    }

    // ---- epilogue: LSTM cell, all 4 gates thread-local ----
    __half* HW = d_Hh + (size_t)(wb * 2 + dir) * NW * HID;
#pragma unroll
    for (int mh = 0; mh < 2; mh++) {
#pragma unroll
        for (int rh = 0; rh < 2; rh++) {
            int s = slot0 + ws * 32 + mh * 16 + rh * 8 + g4;
            if (s >= nact) continue;
            int v = d_chars[dir][t][s];
            const float* Pv = &d_P[((dir << 7) + v) << 10];
            bool last = (t == (int)d_slot_len[s] - 1);
            float* crow = &d_C[((size_t)dir * NW + s) * HID];
            float* frow = &d_Hfin[((size_t)dir * NW + s) * HID];
            __half* hrow = &HW[(size_t)s * HID];
#pragma unroll
            for (int nh = 0; nh < 2; nh++) {
                int jp = j0 + wj * 16 + nh * 8 + 2 * t4;
                float hv[2];
#pragma unroll
                for (int cp = 0; cp < 2; cp++) {
                    int j = jp + cp;
                    float ai = acc[0][nh][mh][rh * 2 + cp] + Pv[j];
                    float af = acc[1][nh][mh][rh * 2 + cp] + Pv[256 + j];
                    float ag = acc[2][nh][mh][rh * 2 + cp] + Pv[512 + j];
                    float ao = acc[3][nh][mh][rh * 2 + cp] + Pv[768 + j];
                    float c2 = sigm(af) * crow[j] + sigm(ai) * tanhf(ag);
                    float h2 = sigm(ao) * tanhf(c2);
                    crow[j] = c2;
                    if (last) frow[j] = h2;
                    hv[cp] = h2;
                }
                __half2 h2v;
                h2v.x = __float2half_rn(hv[0]);
                h2v.y = __float2half_rn(hv[1]);
                *reinterpret_cast<__half2*>(&hrow[jp]) = h2v;
            }
        }
    }
}

// ---------------- gather output ----------------
__global__ void k_out(float* __restrict__ out) {
    int s = blockIdx.x;
    int tid = threadIdx.x;
    int w = d_word_of_slot[s];
    int dir = tid >> 8, j = tid & 255;
    out[(size_t)w * 512 + tid] = d_Hfin[((size_t)dir * NW + s) * HID + j];
}

// ---------------- launch ----------------
extern "C" void kernel_launch(void* const* d_in, const int* in_sizes, int n_in,
                              void* d_out, int out_size) {
    const int*   char_ids = (const int*)d_in[0];
    const int*   lengths  = (const int*)d_in[1];
    const float* emb      = (const float*)d_in[2];
    const float* WihF = (const float*)d_in[3];
    const float* WhhF = (const float*)d_in[4];
    const float* bihF = (const float*)d_in[5];
    const float* bhhF = (const float*)d_in[6];
    const float* WihB = (const float*)d_in[7];
    const float* WhhB = (const float*)d_in[8];
    const float* bihB = (const float*)d_in[9];
    const float* bhhB = (const float*)d_in[10];
    float* out = (float*)d_out;

    static bool s_init = false;
    if (!s_init) {
        cudaFuncSetAttribute(k_step, cudaFuncAttributeMaxDynamicSharedMemorySize, SM_TOT);
        s_init = true;
    }

    k_setup<<<1, 1024>>>(lengths);
    k_prep<<<2048 + 256, 256>>>(emb, WihF, bihF, bhhF, WihB, bihB, bhhB, WhhF, WhhB);
    k_scatter0<<<NW / 64, 512>>>(lengths, char_ids);
    for (int t = 1; t < MAXLEN; t++)
        k_step<<<dim3(NW / 128, 8, 2), 256, SM_TOT>>>(t);
    k_out<<<NW, 512>>>(out);
}